// round 1
// baseline (speedup 1.0000x reference)
#include <cuda_runtime.h>
#include <math.h>

#define W    512
#define HGT  512
#define HW   (512*512)
#define TW   64
#define TH   64
#define RMAX 10
#define SW   (TW + 2*RMAX)   // 84
#define SH   (TH + 2*RMAX)   // 84
#define NKER 21
#define NTH  256
#define WTOT 243             // sum of all kernel sizes
#define SMEM_BYTES ((SH*SW + SH*TW)*4 + WTOT*8)

typedef unsigned long long u64;

// KSIZES reproduced exactly from the reference (incl. i=19 fp edge: 19*(18/19) rounds to 18.0 -> k=21)
__constant__ int   c_KS[NKER]  = {3,3,3,5,5,7,7,9,9,11,11,13,13,15,15,17,17,19,19,21,21};
__constant__ int   c_OFF[NKER] = {0,3,6,9,14,19,26,33,42,51,62,73,86,99,114,129,146,163,182,201,222};
__constant__ float c_SIG[NKER] = {0.500f,0.525f,0.550f,0.575f,0.600f,0.625f,0.650f,0.675f,0.700f,0.725f,
                                  0.750f,0.775f,0.800f,0.825f,0.850f,0.875f,0.900f,0.925f,0.950f,0.975f,1.000f};

__device__ __forceinline__ u64 pack2(float lo, float hi) {
    u64 d; asm("mov.b64 %0, {%1, %2};" : "=l"(d) : "f"(lo), "f"(hi)); return d;
}
__device__ __forceinline__ void fma2(u64& d, u64 a, u64 b) {
    asm("fma.rn.f32x2 %0, %1, %2, %0;" : "+l"(d) : "l"(a), "l"(b));
}
union F2 { u64 u; float2 f; };
union Q4 { float4 q; u64 u[2]; };

__device__ __forceinline__ int refl(int v) {
    if (v < 0)    v = -v;
    if (v >= 512) v = 1022 - v;
    return v;
}

// One separable blur of the resident tile. K compile-time.
template<int K>
__device__ __forceinline__ void blur_one(const float* __restrict__ s_in,
                                         float* __restrict__ s_mid,
                                         const u64* __restrict__ w2,
                                         float* __restrict__ outp,
                                         int x0, int y0, int tid) {
    constexpr int R = (K - 1) / 2;
    constexpr int MROWS = TH + 2*R;    // mid rows needed by vertical pass

    // ---- horizontal pass: each task = 2 rows x 4 cols, row-pairs packed in f32x2 ----
    const int NT = (MROWS/2) * (TW/4);
    for (int t = tid; t < NT; t += NTH) {
        int rp = t >> 4;       // TW/4 == 16
        int cg = t & 15;
        int r  = rp * 2;
        int c0 = cg * 4;
        const float* p0 = s_in + (r + (RMAX - R)) * SW + (c0 + (RMAX - R));
        const float* p1 = p0 + SW;
        u64 v0 = pack2(p0[0], p1[0]);
        u64 v1 = pack2(p0[1], p1[1]);
        u64 v2 = pack2(p0[2], p1[2]);
        u64 v3 = pack2(p0[3], p1[3]);
        u64 a0 = 0, a1 = 0, a2 = 0, a3 = 0;
        #pragma unroll
        for (int j = 0; j < K; ++j) {
            u64 wj = w2[j];
            fma2(a0, wj, v0); fma2(a1, wj, v1);
            fma2(a2, wj, v2); fma2(a3, wj, v3);
            if (j < K - 1) {
                v0 = v1; v1 = v2; v2 = v3;
                v3 = pack2(p0[j + 4], p1[j + 4]);
            }
        }
        F2 f0, f1, f2_, f3; f0.u = a0; f1.u = a1; f2_.u = a2; f3.u = a3;
        *(float4*)(s_mid +  r      * TW + c0) = make_float4(f0.f.x, f1.f.x, f2_.f.x, f3.f.x);
        *(float4*)(s_mid + (r + 1) * TW + c0) = make_float4(f0.f.y, f1.f.y, f2_.f.y, f3.f.y);
    }
    __syncthreads();

    // ---- vertical pass: each thread = 4 rows x 4 cols, col-pairs via LDS.128 ----
    {
        int r0 = (tid >> 4) * 4;
        int c0 = (tid & 15) * 4;
        const float* mp = s_mid + r0 * TW + c0;
        Q4 q;
        q.q = *(const float4*)(mp + 0 * TW); u64 va0 = q.u[0], vb0 = q.u[1];
        q.q = *(const float4*)(mp + 1 * TW); u64 va1 = q.u[0], vb1 = q.u[1];
        q.q = *(const float4*)(mp + 2 * TW); u64 va2 = q.u[0], vb2 = q.u[1];
        q.q = *(const float4*)(mp + 3 * TW); u64 va3 = q.u[0], vb3 = q.u[1];
        u64 A0=0,A1=0,A2=0,A3=0,B0=0,B1=0,B2=0,B3=0;
        #pragma unroll
        for (int j = 0; j < K; ++j) {
            u64 wj = w2[j];
            fma2(A0, wj, va0); fma2(B0, wj, vb0);
            fma2(A1, wj, va1); fma2(B1, wj, vb1);
            fma2(A2, wj, va2); fma2(B2, wj, vb2);
            fma2(A3, wj, va3); fma2(B3, wj, vb3);
            if (j < K - 1) {
                va0 = va1; vb0 = vb1; va1 = va2; vb1 = vb2; va2 = va3; vb2 = vb3;
                q.q = *(const float4*)(mp + (j + 4) * TW); va3 = q.u[0]; vb3 = q.u[1];
            }
        }
        float* o = outp + (size_t)(y0 + r0) * W + (x0 + c0);
        F2 a, b;
        a.u = A0; b.u = B0; *(float4*)(o + 0 * W) = make_float4(a.f.x, a.f.y, b.f.x, b.f.y);
        a.u = A1; b.u = B1; *(float4*)(o + 1 * W) = make_float4(a.f.x, a.f.y, b.f.x, b.f.y);
        a.u = A2; b.u = B2; *(float4*)(o + 2 * W) = make_float4(a.f.x, a.f.y, b.f.x, b.f.y);
        a.u = A3; b.u = B3; *(float4*)(o + 3 * W) = make_float4(a.f.x, a.f.y, b.f.x, b.f.y);
    }
    __syncthreads();
}

__global__ void __launch_bounds__(NTH, 3)
gauss_fused(const float* __restrict__ x, float* __restrict__ out) {
    extern __shared__ float smem[];
    float* s_in  = smem;                    // SH*SW floats
    float* s_mid = smem + SH * SW;          // SH*TW floats
    u64*   s_w2  = (u64*)(smem + SH * SW + SH * TW);  // WTOT packed weight pairs

    int tid = threadIdx.x;

    // Per-CTA weight computation (avoids non-capturable memcpy-to-symbol)
    if (tid < NKER) {
        int K = c_KS[tid];
        float sg = c_SIG[tid];
        int off  = c_OFF[tid];
        float s2 = 2.0f * sg * sg;
        int h = K / 2;
        float sum = 0.0f;
        for (int j = 0; j < K; ++j) { float d = (float)(j - h); sum += expf(-d * d / s2); }
        for (int j = 0; j < K; ++j) {
            float d = (float)(j - h);
            float w = expf(-d * d / s2) / sum;
            s_w2[off + j] = pack2(w, w);
        }
    }

    int z = blockIdx.z;                // b*3 + c
    int b = z / 3, c = z - 3 * b;
    int x0 = blockIdx.x * TW, y0 = blockIdx.y * TH;
    const float* xin = x + (size_t)z * HW;

    // Load 84x84 halo tile once (reflect at image borders), reused by all 21 filters
    for (int idx = tid; idx < SH * SW; idx += NTH) {
        int ly = idx / SW, lx = idx - ly * SW;
        int gy = refl(y0 + ly - RMAX);
        int gx = refl(x0 + lx - RMAX);
        s_in[idx] = xin[gy * W + gx];
    }
    __syncthreads();

    #pragma unroll 1
    for (int i = 0; i < NKER; ++i) {
        float* outp = out + (size_t)(b * 66 + 3 + 3 * i + c) * HW;
        const u64* w2 = s_w2 + c_OFF[i];
        switch (c_KS[i]) {
            case 3:  blur_one<3 >(s_in, s_mid, w2, outp, x0, y0, tid); break;
            case 5:  blur_one<5 >(s_in, s_mid, w2, outp, x0, y0, tid); break;
            case 7:  blur_one<7 >(s_in, s_mid, w2, outp, x0, y0, tid); break;
            case 9:  blur_one<9 >(s_in, s_mid, w2, outp, x0, y0, tid); break;
            case 11: blur_one<11>(s_in, s_mid, w2, outp, x0, y0, tid); break;
            case 13: blur_one<13>(s_in, s_mid, w2, outp, x0, y0, tid); break;
            case 15: blur_one<15>(s_in, s_mid, w2, outp, x0, y0, tid); break;
            case 17: blur_one<17>(s_in, s_mid, w2, outp, x0, y0, tid); break;
            case 19: blur_one<19>(s_in, s_mid, w2, outp, x0, y0, tid); break;
            case 21: blur_one<21>(s_in, s_mid, w2, outp, x0, y0, tid); break;
        }
    }
}

// Identity channels: out[b][0..2] = x[b][0..2]
__global__ void copy_id(const float* __restrict__ x, float* __restrict__ out) {
    int plane = blockIdx.y;            // 0..23 = b*3+c
    int b = plane / 3, c = plane - 3 * b;
    const float4* src = (const float4*)(x + (size_t)plane * HW);
    float4*       dst = (float4*)(out + (size_t)(b * 66 + c) * HW);
    int i = blockIdx.x * blockDim.x + threadIdx.x;   // grid sized to cover HW/4 exactly
    dst[i] = src[i];
}

extern "C" void kernel_launch(void* const* d_in, const int* in_sizes, int n_in,
                              void* d_out, int out_size) {
    const float* x = (const float*)d_in[0];
    float* out = (float*)d_out;

    cudaFuncSetAttribute(gauss_fused, cudaFuncAttributeMaxDynamicSharedMemorySize, SMEM_BYTES);

    dim3 cgrid(HW / 4 / NTH, 24);      // 64 blocks x 24 planes
    copy_id<<<cgrid, NTH>>>(x, out);

    dim3 grid(W / TW, HGT / TH, 24);   // 8 x 8 x 24
    gauss_fused<<<grid, NTH, SMEM_BYTES>>>(x, out);
}

// round 3
// speedup vs baseline: 1.0936x; 1.0936x over previous
#include <cuda_runtime.h>
#include <math.h>

#define W    512
#define HGT  512
#define HW   (512*512)
#define TW   64
#define TH   128
#define RMAX 10
#define SW   84               // TW + 2*RMAX
#define SH   (TH + 2*RMAX)    // 148
#define MW   68               // padded mid width (17 float4, odd -> conflict-free)
#define NKER 21
#define NTH  256
#define WTOT 243
#define SMEM_BYTES ((SH*SW + SH*MW)*4 + WTOT*8)

typedef unsigned long long u64;

// KSIZES reproduced exactly from the reference (incl. i=19 fp edge -> k=21)
__constant__ int   c_KS[NKER]  = {3,3,3,5,5,7,7,9,9,11,11,13,13,15,15,17,17,19,19,21,21};
__constant__ int   c_OFF[NKER] = {0,3,6,9,14,19,26,33,42,51,62,73,86,99,114,129,146,163,182,201,222};
__constant__ float c_SIG[NKER] = {0.500f,0.525f,0.550f,0.575f,0.600f,0.625f,0.650f,0.675f,0.700f,0.725f,
                                  0.750f,0.775f,0.800f,0.825f,0.850f,0.875f,0.900f,0.925f,0.950f,0.975f,1.000f};

__device__ __forceinline__ u64 pack2(float lo, float hi) {
    u64 d; asm("mov.b64 %0, {%1, %2};" : "=l"(d) : "f"(lo), "f"(hi)); return d;
}
__device__ __forceinline__ void fma2(u64& d, u64 a, u64 b) {
    asm("fma.rn.f32x2 %0, %1, %2, %0;" : "+l"(d) : "l"(a), "l"(b));
}
union F2 { u64 u; float2 f; };

__device__ __forceinline__ int refl(int v) {
    if (v < 0)    v = -v;
    if (v >= 512) v = 1022 - v;
    return v;
}

// One separable blur of the resident tile. K compile-time.
template<int K>
__device__ __forceinline__ void blur_one(const float* __restrict__ s_in,
                                         float* __restrict__ s_mid,
                                         const u64* __restrict__ w2,
                                         float* __restrict__ outp,
                                         int x0, int y0, int tid) {
    constexpr int R     = (K - 1) / 2;
    constexpr int MROWS = TH + 2 * R;
    constexpr int HK    = (K + 1) / 2;       // symmetric weight half
    constexpr int D     = (RMAX - R) & 3;    // misalignment of window start (cols)
    constexpr int COL0  = (RMAX - R) - D;    // aligned base col offset
    constexpr int NV    = D + K + 15;        // floats needed per H window
    constexpr int NW4   = (NV + 3) / 4;
    constexpr int ROW0  = RMAX - R;          // s_in row offset for mid row 0

    // weights -> registers (symmetric half), packed f32x2
    u64 wr[HK];
    #pragma unroll
    for (int j = 0; j < HK; ++j) wr[j] = w2[j];

    // ---- horizontal: 1 mid row x 16 cols per task, f32x2 column pairs ----
    // lane map: row = lane&7, colgrp = lane>>3 -> conflict-free LDS.128 on 84-wide rows
    {
        int lane = tid & 31, wid = tid >> 5;
        int lr = lane & 7, cg = lane >> 3;
        constexpr int NCH = (MROWS + 7) / 8;
        for (int ch = wid; ch < NCH; ch += 8) {
            int r = ch * 8 + lr;
            if (r < MROWS) {
                const float4* src = (const float4*)(s_in + (r + ROW0) * SW + cg * 16 + COL0);
                float v[NW4 * 4];
                #pragma unroll
                for (int i = 0; i < NW4; ++i) *(float4*)&v[4 * i] = src[i];
                u64 a[8];
                #pragma unroll
                for (int g = 0; g < 8; ++g) a[g] = 0;
                // streaming: each pack built once, consumed by <=8 accumulators
                #pragma unroll
                for (int m = 0; m < K + 14; ++m) {
                    u64 p = pack2(v[D + m], v[D + m + 1]);
                    #pragma unroll
                    for (int g = 0; g < 8; ++g) {
                        int j = m - 2 * g;
                        if (j >= 0 && j < K)
                            fma2(a[g], wr[(j < HK) ? j : (K - 1 - j)], p);
                    }
                }
                float4* dst = (float4*)(s_mid + r * MW + cg * 16);
                #pragma unroll
                for (int g = 0; g < 4; ++g) {
                    F2 f0, f1; f0.u = a[2 * g]; f1.u = a[2 * g + 1];
                    dst[g] = make_float4(f0.f.x, f0.f.y, f1.f.x, f1.f.y);
                }
            }
        }
    }
    __syncthreads();

    // ---- vertical: 16 rows x 2 cols per thread, each mid value read ONCE ----
    {
        int cp = tid & 31;
        int r0 = (tid >> 5) * 16;
        const float* mp = s_mid + r0 * MW + cp * 2;
        u64 acc[16];
        #pragma unroll
        for (int r = 0; r < 16; ++r) acc[r] = 0;
        #pragma unroll
        for (int m = 0; m < K + 15; ++m) {
            u64 val = *(const u64*)(mp + m * MW);
            #pragma unroll
            for (int r = 0; r < 16; ++r) {
                int j = m - r;
                if (j >= 0 && j < K)
                    fma2(acc[r], wr[(j < HK) ? j : (K - 1 - j)], val);
            }
        }
        float* o = outp + (size_t)(y0 + r0) * W + (x0 + cp * 2);
        #pragma unroll
        for (int r = 0; r < 16; ++r) {
            F2 f; f.u = acc[r];
            *(float2*)(o + (size_t)r * W) = f.f;
        }
    }
    __syncthreads();
}

__global__ void __launch_bounds__(NTH, 2)
gauss_fused(const float* __restrict__ x, float* __restrict__ out) {
    extern __shared__ float smem[];
    float* s_in  = smem;                         // SH*SW
    float* s_mid = smem + SH * SW;               // SH*MW
    u64*   s_w2  = (u64*)(smem + SH * SW + SH * MW);

    int tid = threadIdx.x;

    // per-CTA weight computation (graph-capturable, no memcpyToSymbol)
    if (tid < NKER) {
        int K = c_KS[tid];
        float sg = c_SIG[tid];
        int off = c_OFF[tid];
        float s2 = 2.0f * sg * sg;
        int h = K / 2;
        float sum = 0.0f;
        for (int j = 0; j < K; ++j) { float d = (float)(j - h); sum += expf(-d * d / s2); }
        for (int j = 0; j < K; ++j) {
            float d = (float)(j - h);
            float w = expf(-d * d / s2) / sum;
            s_w2[off + j] = pack2(w, w);
        }
    }

    int z = blockIdx.z;                 // b*3 + c
    int b = z / 3, c = z - 3 * b;
    int x0 = blockIdx.x * TW, y0 = blockIdx.y * TH;
    const float* xin = x + (size_t)z * HW;

    // load 84x148 halo tile once (reflect), reused by all 21 filters
    for (int idx = tid; idx < SH * SW; idx += NTH) {
        int ly = idx / SW, lx = idx - ly * SW;
        int gy = refl(y0 + ly - RMAX);
        int gx = refl(x0 + lx - RMAX);
        s_in[idx] = xin[gy * W + gx];
    }
    __syncthreads();

    #pragma unroll 1
    for (int i = 0; i < NKER; ++i) {
        float* outp = out + (size_t)(b * 66 + 3 + 3 * i + c) * HW;
        const u64* w2 = s_w2 + c_OFF[i];
        switch (c_KS[i]) {
            case 3:  blur_one<3 >(s_in, s_mid, w2, outp, x0, y0, tid); break;
            case 5:  blur_one<5 >(s_in, s_mid, w2, outp, x0, y0, tid); break;
            case 7:  blur_one<7 >(s_in, s_mid, w2, outp, x0, y0, tid); break;
            case 9:  blur_one<9 >(s_in, s_mid, w2, outp, x0, y0, tid); break;
            case 11: blur_one<11>(s_in, s_mid, w2, outp, x0, y0, tid); break;
            case 13: blur_one<13>(s_in, s_mid, w2, outp, x0, y0, tid); break;
            case 15: blur_one<15>(s_in, s_mid, w2, outp, x0, y0, tid); break;
            case 17: blur_one<17>(s_in, s_mid, w2, outp, x0, y0, tid); break;
            case 19: blur_one<19>(s_in, s_mid, w2, outp, x0, y0, tid); break;
            case 21: blur_one<21>(s_in, s_mid, w2, outp, x0, y0, tid); break;
        }
    }
}

// identity channels: out[b][0..2] = x[b][0..2]
__global__ void copy_id(const float* __restrict__ x, float* __restrict__ out) {
    int plane = blockIdx.y;             // b*3 + c
    int b = plane / 3, c = plane - 3 * b;
    const float4* src = (const float4*)(x + (size_t)plane * HW);
    float4*       dst = (float4*)(out + (size_t)(b * 66 + c) * HW);
    int i = blockIdx.x * blockDim.x + threadIdx.x;
    dst[i] = src[i];
}

extern "C" void kernel_launch(void* const* d_in, const int* in_sizes, int n_in,
                              void* d_out, int out_size) {
    const float* x = (const float*)d_in[0];
    float* out = (float*)d_out;

    cudaFuncSetAttribute(gauss_fused, cudaFuncAttributeMaxDynamicSharedMemorySize, SMEM_BYTES);

    dim3 cgrid(HW / 4 / NTH, 24);
    copy_id<<<cgrid, NTH>>>(x, out);

    dim3 grid(W / TW, HGT / TH, 24);    // 8 x 4 x 24
    gauss_fused<<<grid, NTH, SMEM_BYTES>>>(x, out);
}

// round 4
// speedup vs baseline: 1.1500x; 1.0515x over previous
#include <cuda_runtime.h>
#include <math.h>

#define W    512
#define HGT  512
#define HW   (512*512)
#define TW   64
#define TH   64
#define RMAX 10
#define SW   84               // TW + 2*RMAX
#define SH   (TH + 2*RMAX)    // 84
#define MW   68               // padded mid width (17 float4, odd -> conflict-free)
#define NKER 21
#define NTH  256
#define WTOT 243
#define SMEM_BYTES ((SH*SW + SH*MW)*4 + WTOT*8)

typedef unsigned long long u64;

// KSIZES reproduced exactly from the reference (incl. i=19 fp edge -> k=21)
__constant__ int   c_KS[NKER]  = {3,3,3,5,5,7,7,9,9,11,11,13,13,15,15,17,17,19,19,21,21};
__constant__ int   c_OFF[NKER] = {0,3,6,9,14,19,26,33,42,51,62,73,86,99,114,129,146,163,182,201,222};
__constant__ float c_SIG[NKER] = {0.500f,0.525f,0.550f,0.575f,0.600f,0.625f,0.650f,0.675f,0.700f,0.725f,
                                  0.750f,0.775f,0.800f,0.825f,0.850f,0.875f,0.900f,0.925f,0.950f,0.975f,1.000f};

__device__ __forceinline__ u64 pack2(float lo, float hi) {
    u64 d; asm("mov.b64 %0, {%1, %2};" : "=l"(d) : "f"(lo), "f"(hi)); return d;
}
__device__ __forceinline__ void fma2(u64& d, u64 a, u64 b) {
    asm("fma.rn.f32x2 %0, %1, %2, %0;" : "+l"(d) : "l"(a), "l"(b));
}
union F2 { u64 u; float2 f; };

__device__ __forceinline__ int refl(int v) {
    if (v < 0)    v = -v;
    if (v >= 512) v = 1022 - v;
    return v;
}

// One separable blur of the resident tile. K compile-time.
template<int K>
__device__ __forceinline__ void blur_one(const float* __restrict__ s_in,
                                         float* __restrict__ s_mid,
                                         const u64* __restrict__ w2,
                                         float* __restrict__ outp,
                                         int x0, int y0, int tid) {
    constexpr int R     = (K - 1) / 2;
    constexpr int MROWS = TH + 2 * R;        // <= 84
    constexpr int HK    = (K + 1) / 2;       // symmetric weight half
    constexpr int D     = (RMAX - R) & 3;    // misalignment of window start (cols)
    constexpr int COL0  = (RMAX - R) - D;    // aligned base col offset
    constexpr int NV    = D + K + 15;        // floats needed per H window
    constexpr int NW4   = (NV + 3) / 4;
    constexpr int ROW0  = RMAX - R;          // s_in row offset for mid row 0

    // weights -> registers (symmetric half), packed f32x2
    u64 wr[HK];
    #pragma unroll
    for (int j = 0; j < HK; ++j) wr[j] = w2[j];

    // ---- horizontal: 1 mid row x 16 cols per task, f32x2 column pairs ----
    // lane map: row = lane&7, colgrp = lane>>3 -> conflict-free LDS.128 on 84-wide rows
    {
        int lane = tid & 31, wid = tid >> 5;
        int lr = lane & 7, cg = lane >> 3;
        constexpr int NCH = (MROWS + 7) / 8;
        #pragma unroll
        for (int ch = wid; ch < NCH; ch += 8) {
            int r = ch * 8 + lr;
            if (r < MROWS) {
                const float4* src = (const float4*)(s_in + (r + ROW0) * SW + cg * 16 + COL0);
                float v[NW4 * 4];
                #pragma unroll
                for (int i = 0; i < NW4; ++i) *(float4*)&v[4 * i] = src[i];
                u64 a[8];
                #pragma unroll
                for (int g = 0; g < 8; ++g) a[g] = 0;
                // streaming: each pack built once, consumed by <=8 accumulators
                #pragma unroll
                for (int m = 0; m < K + 14; ++m) {
                    u64 p = pack2(v[D + m], v[D + m + 1]);
                    #pragma unroll
                    for (int g = 0; g < 8; ++g) {
                        int j = m - 2 * g;
                        if (j >= 0 && j < K)
                            fma2(a[g], wr[(j < HK) ? j : (K - 1 - j)], p);
                    }
                }
                float4* dst = (float4*)(s_mid + r * MW + cg * 16);
                #pragma unroll
                for (int g = 0; g < 4; ++g) {
                    F2 f0, f1; f0.u = a[2 * g]; f1.u = a[2 * g + 1];
                    dst[g] = make_float4(f0.f.x, f0.f.y, f1.f.x, f1.f.y);
                }
            }
        }
    }
    __syncthreads();

    // ---- vertical: 8 rows x 2 cols per thread, each mid value read once per 8 rows ----
    {
        int cp = tid & 31;
        int r0 = (tid >> 5) * 8;
        const float* mp = s_mid + r0 * MW + cp * 2;
        u64 acc[8];
        #pragma unroll
        for (int r = 0; r < 8; ++r) acc[r] = 0;
        #pragma unroll
        for (int m = 0; m < K + 7; ++m) {
            u64 val = *(const u64*)(mp + m * MW);
            #pragma unroll
            for (int r = 0; r < 8; ++r) {
                int j = m - r;
                if (j >= 0 && j < K)
                    fma2(acc[r], wr[(j < HK) ? j : (K - 1 - j)], val);
            }
        }
        float* o = outp + (size_t)(y0 + r0) * W + (x0 + cp * 2);
        #pragma unroll
        for (int r = 0; r < 8; ++r) {
            F2 f; f.u = acc[r];
            *(float2*)(o + (size_t)r * W) = f.f;
        }
    }
    __syncthreads();
}

__global__ void __launch_bounds__(NTH, 3)
gauss_fused(const float* __restrict__ x, float* __restrict__ out) {
    extern __shared__ float smem[];
    float* s_in  = smem;                         // SH*SW
    float* s_mid = smem + SH * SW;               // SH*MW
    u64*   s_w2  = (u64*)(smem + SH * SW + SH * MW);

    int tid = threadIdx.x;

    // per-CTA weight computation (graph-capturable, no memcpyToSymbol)
    if (tid < NKER) {
        int K = c_KS[tid];
        float sg = c_SIG[tid];
        int off = c_OFF[tid];
        float s2 = 2.0f * sg * sg;
        int h = K / 2;
        float sum = 0.0f;
        for (int j = 0; j < K; ++j) { float d = (float)(j - h); sum += expf(-d * d / s2); }
        for (int j = 0; j < K; ++j) {
            float d = (float)(j - h);
            float w = expf(-d * d / s2) / sum;
            s_w2[off + j] = pack2(w, w);
        }
    }

    int z = blockIdx.z;                 // b*3 + c
    int b = z / 3, c = z - 3 * b;
    int x0 = blockIdx.x * TW, y0 = blockIdx.y * TH;
    const float* xin = x + (size_t)z * HW;

    // load 84x84 halo tile once (reflect), reused by all 21 filters
    for (int idx = tid; idx < SH * SW; idx += NTH) {
        int ly = idx / SW, lx = idx - ly * SW;
        int gy = refl(y0 + ly - RMAX);
        int gx = refl(x0 + lx - RMAX);
        s_in[idx] = xin[gy * W + gx];
    }
    __syncthreads();

    #pragma unroll 1
    for (int i = 0; i < NKER; ++i) {
        float* outp = out + (size_t)(b * 66 + 3 + 3 * i + c) * HW;
        const u64* w2 = s_w2 + c_OFF[i];
        switch (c_KS[i]) {
            case 3:  blur_one<3 >(s_in, s_mid, w2, outp, x0, y0, tid); break;
            case 5:  blur_one<5 >(s_in, s_mid, w2, outp, x0, y0, tid); break;
            case 7:  blur_one<7 >(s_in, s_mid, w2, outp, x0, y0, tid); break;
            case 9:  blur_one<9 >(s_in, s_mid, w2, outp, x0, y0, tid); break;
            case 11: blur_one<11>(s_in, s_mid, w2, outp, x0, y0, tid); break;
            case 13: blur_one<13>(s_in, s_mid, w2, outp, x0, y0, tid); break;
            case 15: blur_one<15>(s_in, s_mid, w2, outp, x0, y0, tid); break;
            case 17: blur_one<17>(s_in, s_mid, w2, outp, x0, y0, tid); break;
            case 19: blur_one<19>(s_in, s_mid, w2, outp, x0, y0, tid); break;
            case 21: blur_one<21>(s_in, s_mid, w2, outp, x0, y0, tid); break;
        }
    }
}

// identity channels: out[b][0..2] = x[b][0..2]
__global__ void copy_id(const float* __restrict__ x, float* __restrict__ out) {
    int plane = blockIdx.y;             // b*3 + c
    int b = plane / 3, c = plane - 3 * b;
    const float4* src = (const float4*)(x + (size_t)plane * HW);
    float4*       dst = (float4*)(out + (size_t)(b * 66 + c) * HW);
    int i = blockIdx.x * blockDim.x + threadIdx.x;
    dst[i] = src[i];
}

extern "C" void kernel_launch(void* const* d_in, const int* in_sizes, int n_in,
                              void* d_out, int out_size) {
    const float* x = (const float*)d_in[0];
    float* out = (float*)d_out;

    cudaFuncSetAttribute(gauss_fused, cudaFuncAttributeMaxDynamicSharedMemorySize, SMEM_BYTES);

    dim3 cgrid(HW / 4 / NTH, 24);
    copy_id<<<cgrid, NTH>>>(x, out);

    dim3 grid(W / TW, HGT / TH, 24);    // 8 x 8 x 24
    gauss_fused<<<grid, NTH, SMEM_BYTES>>>(x, out);
}